// round 14
// baseline (speedup 1.0000x reference)
#include <cuda_runtime.h>

#define NP  66
#define NPP 72

// ---------------- scratch (no allocations allowed) ----------------
__device__ __align__(16) float g_O0[8 * NP * 32 * 32];
__device__ __align__(16) float g_O1[8 * NP * 64 * 64];
__device__ __align__(16) float g_O2[8 * NP * 128 * 128];

// Precomputed OvO vote masks over the 66 pairs (+pad bits always 0).
__constant__ int4 c_MA[12] = {
  {0x000007FF, 0x00000000, 0x0, 0x00000000},
  {0x001FF800, 0x00000000, 0x0, 0x00000001},
  {0x3FE00000, 0x00000000, 0x0, 0x00000802},
  {(int)0xC0000000, 0x0000003F, 0x0, 0x00201004},
  {0x00000000, 0x00001FC0, 0x0, 0x40402008},
  {0x00000000, 0x0007E000, 0x0, (int)0x80804010},
  {0x00000000, 0x00F80000, 0x0, 0x01008020},
  {0x00000000, 0x0F000000, 0x0, 0x02010040},
  {0x00000000, 0x70000000, 0x0, 0x04020080},
  {0x00000000, (int)0x80000000, 0x1, 0x08040100},
  {0x00000000, 0x00000000, 0x2, 0x10080200},
  {0x00000000, 0x00000000, 0x0, 0x20100400}};
__constant__ int4 c_MB[12] = {
  {0x00000000, 0x0, 0, 0}, {0x00000000, 0x0, 0, 0},
  {0x00000000, 0x0, 0, 0}, {0x00000000, 0x0, 0, 0},
  {0x00000000, 0x0, 0, 0}, {0x00000040, 0x0, 0, 0},
  {0x00002081, 0x0, 0, 0}, {0x00084102, 0x0, 0, 0},
  {0x01108204, 0x0, 0, 0}, {0x12210408, 0x0, 0, 0},
  {(int)0xA4420810, 0x0, 0, 0}, {0x48841020, 0x3, 0, 0}};

// bilinear y-tables (indexed by tile row r) — constant port, not regs/L1
__constant__ float c_WY[24] = {
  .75f, .25f, .75f, .25f, .75f, .25f, .75f, .25f,                  // L2 (f=2)
  .625f, .875f, .125f, .375f, .625f, .875f, .125f, .375f,          // L1 (f=4)
  .5625f, .6875f, .8125f, .9375f, .0625f, .1875f, .3125f, .4375f}; // L0 (f=8)
__constant__ int c_RY[24] = {
  0, 1, 1, 2, 2, 3, 3, 4,
  0, 0, 1, 1, 1, 1, 2, 2,
  0, 0, 0, 0, 1, 1, 1, 1};

// ---------------- helpers ----------------
__device__ __forceinline__ void ffma2(unsigned long long& d,
                                      unsigned long long a,
                                      unsigned long long b) {
  asm("fma.rn.f32x2 %0, %1, %2, %0;" : "+l"(d) : "l"(a), "l"(b));
}
__device__ __forceinline__ unsigned long long pack2(float x) {
  unsigned long long r;
  asm("mov.b64 %0, {%1, %1};" : "=l"(r) : "f"(x));
  return r;
}
__device__ __forceinline__ float2 unpack2(unsigned long long u) {
  float2 r;
  asm("mov.b64 {%0, %1}, %2;" : "=f"(r.x), "=f"(r.y) : "l"(u));
  return r;
}
__device__ __forceinline__ unsigned su32(const void* p) {
  return (unsigned)__cvta_generic_to_shared(p);
}
__device__ __forceinline__ void cpa16(unsigned dst, const void* src) {
  asm volatile("cp.async.cg.shared.global [%0], [%1], 16;" :: "r"(dst), "l"(src));
}
__device__ __forceinline__ void cpa4(unsigned dst, const void* src) {
  asm volatile("cp.async.ca.shared.global [%0], [%1], 4;" :: "r"(dst), "l"(src));
}
#define CPA_COMMIT() asm volatile("cp.async.commit_group;" ::: "memory")
#define CPA_WAIT(n)  asm volatile("cp.async.wait_group %0;" :: "n"(n) : "memory")

#define XBUF (8 * 128)
#define WBUF (8 * NPP)

// full 8-pair compute (warps 0..7)
#define COMPUTE8_FULL(Wb, Xb)                                                  \
  _Pragma("unroll")                                                            \
  for (int k = 0; k < 8; k++) {                                                \
    const ulonglong2 xv = *(const ulonglong2*)&(Xb)[k * 128 + 4 * ln];         \
    {                                                                          \
      const float4 wA = *(const float4*)&(Wb)[k * NPP + 8 * wrp];              \
      unsigned long long w0 = pack2(wA.x), w1 = pack2(wA.y);                   \
      unsigned long long w2 = pack2(wA.z), w3 = pack2(wA.w);                   \
      ffma2(acc[0][0], w0, xv.x); ffma2(acc[0][1], w0, xv.y);                  \
      ffma2(acc[1][0], w1, xv.x); ffma2(acc[1][1], w1, xv.y);                  \
      ffma2(acc[2][0], w2, xv.x); ffma2(acc[2][1], w2, xv.y);                  \
      ffma2(acc[3][0], w3, xv.x); ffma2(acc[3][1], w3, xv.y);                  \
    }                                                                          \
    {                                                                          \
      const float4 wB = *(const float4*)&(Wb)[k * NPP + 8 * wrp + 4];          \
      unsigned long long w4 = pack2(wB.x), w5 = pack2(wB.y);                   \
      unsigned long long w6 = pack2(wB.z), w7 = pack2(wB.w);                   \
      ffma2(acc[4][0], w4, xv.x); ffma2(acc[4][1], w4, xv.y);                  \
      ffma2(acc[5][0], w5, xv.x); ffma2(acc[5][1], w5, xv.y);                  \
      ffma2(acc[6][0], w6, xv.x); ffma2(acc[6][1], w6, xv.y);                  \
      ffma2(acc[7][0], w7, xv.x); ffma2(acc[7][1], w7, xv.y);                  \
    }                                                                          \
  }

// light compute for warp 8: only real pairs 64,65
#define COMPUTE8_LIGHT(Wb, Xb)                                                 \
  _Pragma("unroll")                                                            \
  for (int k = 0; k < 8; k++) {                                                \
    const ulonglong2 xv = *(const ulonglong2*)&(Xb)[k * 128 + 4 * ln];         \
    const float2 wv = *(const float2*)&(Wb)[k * NPP + 64];                     \
    unsigned long long w0 = pack2(wv.x), w1 = pack2(wv.y);                     \
    ffma2(acc[0][0], w0, xv.x); ffma2(acc[0][1], w0, xv.y);                    \
    ffma2(acc[1][0], w1, xv.x); ffma2(acc[1][1], w1, xv.y);                    \
  }

// issue loads of channel-chunk j into ring buffer j&3
#define ISSUE_CHUNK(j, XSTRIDE)                                                \
  do {                                                                         \
    int _b = (j) & 3, _c0 = (j) * 8;                                           \
    if (hasx) cpa16(xd0 + _b * (XBUF * 4), xsrc + (size_t)_c0 * (XSTRIDE));    \
    cpa4(wda0 + _b * (WBUF * 4), wsa + _c0);                                   \
    if (hasb) cpa4(wdb0 + _b * (WBUF * 4), wsb + _c0);                         \
  } while (0)

// ---------------- conv body: 66 pairs x 128 px, 4-deep cp.async ring ---------
template <int C, int SS>
__device__ __forceinline__ void conv_body(const float* __restrict__ X,
                                          const float* __restrict__ W,
                                          const float* __restrict__ bias,
                                          float* __restrict__ Og,
                                          int n, int px0,
                                          float* Ws, float* Xs) {
  const int tid = threadIdx.x;
  const int wrp = tid >> 5, ln = tid & 31;

  unsigned long long acc[8][2];
#pragma unroll
  for (int a = 0; a < 8; a++) {
    int p = 8 * wrp + a;
    unsigned long long pk = pack2((p < NP) ? bias[p] : 0.0f);
    acc[a][0] = pk; acc[a][1] = pk;
  }

  const bool hasx = tid < 256;
  const int ch_ = tid >> 5, t_ = tid & 31;
  const unsigned xd0 = su32(&Xs[ch_ * 128 + 4 * t_]);
  const float* xsrc = X + (size_t)n * C * SS + px0 + (size_t)ch_ * SS + 4 * t_;

  const int ka = tid / 66, pa = tid - 66 * ka;
  const int sb_ = tid + 288;
  const bool hasb = sb_ < 528;
  const int kb = sb_ / 66, pb = sb_ - 66 * kb;
  const unsigned wda0 = su32(&Ws[ka * NPP + pa]);
  const unsigned wdb0 = su32(&Ws[kb * NPP + pb]);
  const float* wsa = W + pa * C + ka;
  const float* wsb = W + pb * C + kb;

  ISSUE_CHUNK(0, SS); CPA_COMMIT();
  ISSUE_CHUNK(1, SS); CPA_COMMIT();
  ISSUE_CHUNK(2, SS); CPA_COMMIT();

  const int NIT = C / 8;
  for (int i = 0; i < NIT; i++) {
    CPA_WAIT(2);
    __syncthreads();
    {
      const float* Wb = Ws + (i & 3) * WBUF;
      const float* Xb = Xs + (i & 3) * XBUF;
      if (wrp < 8) { COMPUTE8_FULL(Wb, Xb); }
      else         { COMPUTE8_LIGHT(Wb, Xb); }
    }
    if (i + 3 < NIT) ISSUE_CHUNK(i + 3, SS);
    CPA_COMMIT();
  }

  float* On = Og + (size_t)n * NP * SS + px0 + 4 * ln;
#pragma unroll
  for (int a = 0; a < 8; a++) {
    int p = 8 * wrp + a;
    if (p < NP) {
      ulonglong2 v;
      v.x = acc[a][0]; v.y = acc[a][1];
      *(ulonglong2*)&On[(size_t)p * SS] = v;
    }
  }
}

// ---------------- merged conv for stages 0..2 ----------------
__global__ __launch_bounds__(288, 3) void conv_all(
    const float* __restrict__ s0, const float* __restrict__ s1,
    const float* __restrict__ s2, const float* __restrict__ w0,
    const float* __restrict__ w1, const float* __restrict__ w2,
    const float* __restrict__ b0, const float* __restrict__ b1,
    const float* __restrict__ b2) {
  __shared__ __align__(16) float Ws[4 * WBUF];
  __shared__ __align__(16) float Xs[4 * XBUF];
  int bid = blockIdx.x;
  if (bid < 64) {
    conv_body<512, 32 * 32>(s0, w0, b0, g_O0, bid >> 3, (bid & 7) << 7, Ws, Xs);
  } else if (bid < 320) {
    int q = bid - 64;
    conv_body<256, 64 * 64>(s1, w1, b1, g_O1, q >> 5, (q & 31) << 7, Ws, Xs);
  } else {
    int q = bid - 320;
    conv_body<128, 128 * 128>(s2, w2, b2, g_O2, q >> 7, (q & 127) << 7, Ws, Xs);
  }
}

// ---------------- fused: stage3 conv + bilinear pyramid sum + popc vote ------
// tile = 8 rows x 16 cols; warp = 8 pairs, lane = 4-px quad (row=ln>>2, qc=ln&3)
// sO2 rows padded to stride 20 (vs data width 16) to break LDS bank cycling.
__global__ __launch_bounds__(288, 3) void fused_kernel(
    const float* __restrict__ X, const float* __restrict__ W,
    const float* __restrict__ bias, float* __restrict__ out) {
  __shared__ __align__(16) float Ws[4 * WBUF];
  __shared__ __align__(16) float Xs[4 * XBUF];   // reused for sign bytes later
  __shared__ __align__(16) float sO2[NP * 120];  // 6 rows x stride 20 (16 data)
  __shared__ __align__(16) float sO1[NP * 48];   // 4 rows x 12 (base col 4tx-4)
  __shared__ __align__(16) float sO0[NP * 24];   // 3 rows x 8 (base a0x)

  const int tid = threadIdx.x;
  const int wrp = tid >> 5, ln = tid & 31;
  const int n = blockIdx.y;
  const int ty = blockIdx.x >> 4, tx = blockIdx.x & 15;
  const int y0 = ty << 3, x0 = tx << 4;

  // ---- mainloop slot addressing ----
  const bool hasx = tid < 256;
  const int ch_ = tid >> 5, t_ = tid & 31;
  const unsigned xd0 = su32(&Xs[ch_ * 128 + 4 * t_]);
  const float* Xn = X + (size_t)n * 64 * 65536;
  const float* xsrc = Xn + (size_t)ch_ * 65536 + (y0 + (t_ >> 2)) * 256 + x0 + ((t_ & 3) << 2);
  const int ka = tid / 66, pa = tid - 66 * ka;
  const int sb_ = tid + 288;
  const bool hasb = sb_ < 528;
  const int kb = sb_ / 66, pb = sb_ - 66 * kb;
  const unsigned wda0 = su32(&Ws[ka * NPP + pa]);
  const unsigned wdb0 = su32(&Ws[kb * NPP + pb]);
  const float* wsa = W + pa * 64 + ka;
  const float* wsb = W + pb * 64 + kb;

  ISSUE_CHUNK(0, 65536); CPA_COMMIT();
  ISSUE_CHUNK(1, 65536); CPA_COMMIT();
  ISSUE_CHUNK(2, 65536); CPA_COMMIT();

  // ---- sO staging (group 3) ----
  const int by2 = (y0 >> 1) - 1, a2 = 8 * tx - 4;
  const int by1 = (y0 >> 2) - 1, a1 = 4 * tx - 4;
  const int by0 = (y0 >> 3) - 1;
  const int bx0 = 2 * tx - 1, a0x = bx0 & ~3, off0 = bx0 & 3;
  const float* s2g = g_O2 + (size_t)n * NP * 16384;
  const float* s1g = g_O1 + (size_t)n * NP * 4096;
  const float* s0g = g_O0 + (size_t)n * NP * 1024;

  if (tx >= 1 && tx <= 14) {
    for (int i = tid; i < NP * 24; i += 288) {         // O2: 6 rows x 4 chunks
      int p = i / 24, r = i - p * 24;
      int rr = r >> 2, c4 = (r & 3) << 2;
      int sy = min(max(by2 + rr, 0), 127);
      cpa16(su32(&sO2[p * 120 + rr * 20 + c4]), s2g + p * 16384 + sy * 128 + a2 + c4);
    }
    for (int i = tid; i < NP * 12; i += 288) {         // O1: 4 rows x 3 chunks
      int p = i / 12, r = i - p * 12;
      int rr = r / 3, c4 = (r - rr * 3) << 2;
      int sy = min(max(by1 + rr, 0), 63);
      cpa16(su32(&sO1[p * 48 + rr * 12 + c4]), s1g + p * 4096 + sy * 64 + a1 + c4);
    }
    for (int i = tid; i < NP * 6; i += 288) {          // O0: 3 rows x 2 chunks
      int p = i / 6, r = i - p * 6;
      int rr = r >> 1, c4 = (r & 1) << 2;
      int sy = min(max(by0 + rr, 0), 31);
      cpa16(su32(&sO0[p * 24 + rr * 8 + c4]), s0g + p * 1024 + sy * 32 + a0x + c4);
    }
  } else {  // edge tiles: scalar clamped staging (same layouts)
    for (int i = tid; i < NP * 96; i += 288) {
      int p = i / 96, r = i - p * 96;
      int rr = r >> 4, c = r & 15;
      int sy = min(max(by2 + rr, 0), 127);
      int sx = min(max(a2 + c, 0), 127);
      cpa4(su32(&sO2[p * 120 + rr * 20 + c]), s2g + p * 16384 + sy * 128 + sx);
    }
    for (int i = tid; i < NP * 48; i += 288) {
      int p = i / 48, r = i - p * 48;
      int rr = r / 12, c = r - rr * 12;
      int sy = min(max(by1 + rr, 0), 63);
      int sx = min(max(a1 + c, 0), 63);
      cpa4(su32(&sO1[p * 48 + rr * 12 + c]), s1g + p * 4096 + sy * 64 + sx);
    }
    for (int i = tid; i < NP * 24; i += 288) {
      int p = i / 24, r = i - p * 24;
      int rr = r >> 3, c = r & 7;
      int sy = min(max(by0 + rr, 0), 31);
      int sx = min(max(a0x + c, 0), 31);
      cpa4(su32(&sO0[p * 24 + rr * 8 + c]), s0g + p * 1024 + sy * 32 + sx);
    }
  }
  CPA_COMMIT();   // group 3 = staging

  // ---- stage3 GEMM mainloop (C=64), 4-deep cp.async ring ----
  unsigned long long acc[8][2];
#pragma unroll
  for (int a = 0; a < 8; a++) {
    int p = 8 * wrp + a;
    unsigned long long pk = pack2((p < NP) ? bias[p] : 0.0f);
    acc[a][0] = pk; acc[a][1] = pk;
  }

  for (int i = 0; i < 8; i++) {
    CPA_WAIT(2);
    __syncthreads();
    {
      const float* Wb = Ws + (i & 3) * WBUF;
      const float* Xb = Xs + (i & 3) * XBUF;
      if (wrp < 8) { COMPUTE8_FULL(Wb, Xb); }
      else         { COMPUTE8_LIGHT(Wb, Xb); }
    }
    if (i + 3 < 8) ISSUE_CHUNK(i + 3, 65536);
    CPA_COMMIT();
  }
  __syncthreads();  // all compute done; Xs ring now dead -> reuse for signs

  // ---- epilogue: separable bilinear (quad-shared taps) + sign bytes ----
  {
    const int r = ln >> 2, qc = ln & 3;
    const int ry2 = c_RY[r];      const float wy2 = c_WY[r];
    const int ry1 = c_RY[8 + r];  const float wy1 = c_WY[8 + r];
    const int ry0 = c_RY[16 + r]; const float wy0 = c_WY[16 + r];
    const int w0qc = (qc + 1) >> 1;       // {0,1,1,2}
    const float fx0adj = (qc & 1) ? 0.5f : 0.0f;

    const int   LX2[4] = {0, 1, 1, 2};
    const float FX2[4] = {.75f, .25f, .75f, .25f};
    const int   LX1[4] = {0, 0, 1, 1};
    const float FX1[4] = {.625f, .875f, .125f, .375f};
    const float FX0[4] = {.5625f, .6875f, .8125f, .9375f};

    const int o2 = ry2 * 20 + 3 + 2 * qc;
    const int o1 = ry1 * 12 + 3 + qc;
    const int o0 = ry0 * 8 + off0 + w0qc;

    unsigned by[4] = {0, 0, 0, 0};
#pragma unroll
    for (int a = 0; a < 8; a++) {
      int p = 8 * wrp + a;
      if (p < NP) {
        float v[4];
        float2 u0 = unpack2(acc[a][0]), u1 = unpack2(acc[a][1]);
        v[0] = u0.x; v[1] = u0.y; v[2] = u1.x; v[3] = u1.y;
        const float* A2 = &sO2[p * 120 + o2];
        float t2[4];
#pragma unroll
        for (int t = 0; t < 4; t++) t2[t] = A2[t] + wy2 * (A2[t + 20] - A2[t]);
        const float* A1 = &sO1[p * 48 + o1];
        float t1[3];
#pragma unroll
        for (int t = 0; t < 3; t++) t1[t] = A1[t] + wy1 * (A1[t + 12] - A1[t]);
        const float* A0 = &sO0[p * 24 + o0];
        float t0a = A0[0] + wy0 * (A0[8] - A0[0]);
        float t0b = A0[1] + wy0 * (A0[9] - A0[1]);
#pragma unroll
        for (int q = 0; q < 4; q++) {
          v[q] += t2[LX2[q]] + FX2[q] * (t2[LX2[q] + 1] - t2[LX2[q]]);
          v[q] += t1[LX1[q]] + FX1[q] * (t1[LX1[q] + 1] - t1[LX1[q]]);
          float f0 = FX0[q] - fx0adj;
          v[q] += t0a + f0 * (t0b - t0a);
        }
#pragma unroll
        for (int q = 0; q < 4; q++) by[q] |= ((v[q] > 0.0f) ? 1u : 0u) << a;
      }
    }
    unsigned* sS32 = (unsigned*)Xs;
    sS32[wrp * 32 + ln] = by[0] | (by[1] << 8) | (by[2] << 16) | (by[3] << 24);
  }
  __syncthreads();

  // ---- vote via popcount against constant masks, coalesced store ----
  if (tid < 128) {
    const unsigned char* sb8 = (const unsigned char*)Xs;
    unsigned b0 = sb8[tid],           b1 = sb8[128 + tid];
    unsigned b2 = sb8[256 + tid],     b3 = sb8[384 + tid];
    unsigned b4 = sb8[512 + tid],     b5 = sb8[640 + tid];
    unsigned b6 = sb8[768 + tid],     b7 = sb8[896 + tid];
    unsigned b8 = sb8[1024 + tid];
    unsigned sw0 = b0 | (b1 << 8) | (b2 << 16) | (b3 << 24);
    unsigned sw1 = b4 | (b5 << 8) | (b6 << 16) | (b7 << 24);
    unsigned sw2 = b8;
    int row = tid >> 4, col = tid & 15;
    float* op = out + (size_t)n * 12 * 65536 + (y0 + row) * 256 + (x0 + col);
#pragma unroll
    for (int k = 0; k < 12; k++) {
      int4 A = c_MA[k];
      int4 B = c_MB[k];
      int cnt = __popc(sw0 & (unsigned)A.x) + __popc(sw1 & (unsigned)A.y) +
                __popc(sw2 & (unsigned)A.z) - __popc(sw0 & (unsigned)A.w) -
                __popc(sw1 & (unsigned)B.x) - __popc(sw2 & (unsigned)B.y) + k;
      op[(size_t)k << 16] = (float)cnt;
    }
  }
}

// ---------------- launcher ----------------
extern "C" void kernel_launch(void* const* d_in, const int* in_sizes, int n_in,
                              void* d_out, int out_size) {
  const float* st[4] = {0, 0, 0, 0};
  const float* w[4] = {0, 0, 0, 0};
  const float* bb[4] = {0, 0, 0, 0};
  int bc = 0;
  for (int i = 0; i < n_in; i++) {
    switch (in_sizes[i]) {
      case 4194304:  st[0] = (const float*)d_in[i]; break;  // 8*512*32*32
      case 8388608:  st[1] = (const float*)d_in[i]; break;  // 8*256*64*64
      case 16777216: st[2] = (const float*)d_in[i]; break;  // 8*128*128*128
      case 33554432: st[3] = (const float*)d_in[i]; break;  // 8*64*256*256
      case 33792: w[0] = (const float*)d_in[i]; break;      // 66*512
      case 16896: w[1] = (const float*)d_in[i]; break;      // 66*256
      case 8448:  w[2] = (const float*)d_in[i]; break;      // 66*128
      case 4224:  w[3] = (const float*)d_in[i]; break;      // 66*64
      case 66:
        if (bc < 4) bb[bc++] = (const float*)d_in[i];       // b0..b3 in order
        break;
      default: break;  // last_only (==1 always per setup_inputs)
    }
  }

  // prefer max shared carveout so 3 fused CTAs fit (idempotent, no alloc)
  cudaFuncSetAttribute(fused_kernel,
                       cudaFuncAttributePreferredSharedMemoryCarveout, 100);
  cudaFuncSetAttribute(conv_all,
                       cudaFuncAttributePreferredSharedMemoryCarveout, 100);

  conv_all<<<1344, 288>>>(st[0], st[1], st[2], w[0], w[1], w[2],
                          bb[0], bb[1], bb[2]);
  fused_kernel<<<dim3(512, 8), 288>>>(st[3], w[3], bb[3], (float*)d_out);
}

// round 15
// speedup vs baseline: 1.5558x; 1.5558x over previous
#include <cuda_runtime.h>
#include <cuda.h>

#define NP  66
#define NPP 72

// ---------------- scratch (no allocations allowed) ----------------
__device__ __align__(16) float g_O0[8 * NP * 32 * 32];
__device__ __align__(16) float g_O1[8 * NP * 64 * 64];
__device__ __align__(16) float g_O2[8 * NP * 128 * 128];

// Precomputed OvO vote masks over the 66 pairs (+pad bits always 0).
__constant__ int4 c_MA[12] = {
  {0x000007FF, 0x00000000, 0x0, 0x00000000},
  {0x001FF800, 0x00000000, 0x0, 0x00000001},
  {0x3FE00000, 0x00000000, 0x0, 0x00000802},
  {(int)0xC0000000, 0x0000003F, 0x0, 0x00201004},
  {0x00000000, 0x00001FC0, 0x0, 0x40402008},
  {0x00000000, 0x0007E000, 0x0, (int)0x80804010},
  {0x00000000, 0x00F80000, 0x0, 0x01008020},
  {0x00000000, 0x0F000000, 0x0, 0x02010040},
  {0x00000000, 0x70000000, 0x0, 0x04020080},
  {0x00000000, (int)0x80000000, 0x1, 0x08040100},
  {0x00000000, 0x00000000, 0x2, 0x10080200},
  {0x00000000, 0x00000000, 0x0, 0x20100400}};
__constant__ int4 c_MB[12] = {
  {0x00000000, 0x0, 0, 0}, {0x00000000, 0x0, 0, 0},
  {0x00000000, 0x0, 0, 0}, {0x00000000, 0x0, 0, 0},
  {0x00000000, 0x0, 0, 0}, {0x00000040, 0x0, 0, 0},
  {0x00002081, 0x0, 0, 0}, {0x00084102, 0x0, 0, 0},
  {0x01108204, 0x0, 0, 0}, {0x12210408, 0x0, 0, 0},
  {(int)0xA4420810, 0x0, 0, 0}, {0x48841020, 0x3, 0, 0}};

// bilinear y-tables (indexed by tile row r) — constant port, not regs/L1
__constant__ float c_WY[24] = {
  .75f, .25f, .75f, .25f, .75f, .25f, .75f, .25f,                  // L2 (f=2)
  .625f, .875f, .125f, .375f, .625f, .875f, .125f, .375f,          // L1 (f=4)
  .5625f, .6875f, .8125f, .9375f, .0625f, .1875f, .3125f, .4375f}; // L0 (f=8)
__constant__ int c_RY[24] = {
  0, 1, 1, 2, 2, 3, 3, 4,
  0, 0, 1, 1, 1, 1, 2, 2,
  0, 0, 0, 0, 1, 1, 1, 1};

// ---------------- helpers ----------------
__device__ __forceinline__ void ffma2(unsigned long long& d,
                                      unsigned long long a,
                                      unsigned long long b) {
  asm("fma.rn.f32x2 %0, %1, %2, %0;" : "+l"(d) : "l"(a), "l"(b));
}
__device__ __forceinline__ unsigned long long pack2(float x) {
  unsigned long long r;
  asm("mov.b64 %0, {%1, %1};" : "=l"(r) : "f"(x));
  return r;
}
__device__ __forceinline__ float2 unpack2(unsigned long long u) {
  float2 r;
  asm("mov.b64 {%0, %1}, %2;" : "=f"(r.x), "=f"(r.y) : "l"(u));
  return r;
}
__device__ __forceinline__ unsigned su32(const void* p) {
  return (unsigned)__cvta_generic_to_shared(p);
}
__device__ __forceinline__ void cpa16(unsigned dst, const void* src) {
  asm volatile("cp.async.cg.shared.global [%0], [%1], 16;" :: "r"(dst), "l"(src));
}
__device__ __forceinline__ void cpa4(unsigned dst, const void* src) {
  asm volatile("cp.async.ca.shared.global [%0], [%1], 4;" :: "r"(dst), "l"(src));
}
#define CPA_COMMIT() asm volatile("cp.async.commit_group;" ::: "memory")
#define CPA_WAIT(n)  asm volatile("cp.async.wait_group %0;" :: "n"(n) : "memory")

#define MBAR_INIT(addr, cnt) \
  asm volatile("mbarrier.init.shared.b64 [%0], %1;" :: "r"(addr), "r"(cnt) : "memory")
#define MBAR_EXPECT(addr, bytes) \
  asm volatile("mbarrier.arrive.expect_tx.shared.b64 _, [%0], %1;" :: "r"(addr), "r"(bytes) : "memory")
#define MBAR_WAIT(addr, par) do {                                              \
  unsigned _m = (addr), _p = (par), _d;                                        \
  asm volatile("{\n\t.reg .pred p;\n\t"                                        \
    "mbarrier.try_wait.parity.acquire.cta.shared::cta.b64 p, [%1], %2;\n\t"    \
    "selp.b32 %0, 1, 0, p;\n\t}" : "=r"(_d) : "r"(_m), "r"(_p) : "memory");    \
  if (!_d) {                                                                   \
    asm volatile("{\n\t.reg .pred P1;\n\t"                                     \
      "WL_%=:\n\t"                                                             \
      "mbarrier.try_wait.parity.acquire.cta.shared::cta.b64 P1, [%0], %1, 0x989680;\n\t" \
      "@P1 bra.uni WD_%=;\n\t"                                                 \
      "bra.uni WL_%=;\n\t"                                                     \
      "WD_%=:\n\t}" :: "r"(_m), "r"(_p) : "memory");                           \
  }                                                                            \
} while (0)

__device__ __forceinline__ void tma3d(unsigned dst, const CUtensorMap* map,
                                      int cx, int cy, int cz, unsigned mbar) {
  asm volatile(
      "cp.async.bulk.tensor.3d.shared::cta.global.tile.mbarrier::complete_tx::bytes "
      "[%0], [%1, {%2, %3, %4}], [%5];"
      :: "r"(dst), "l"(map), "r"(cx), "r"(cy), "r"(cz), "r"(mbar)
      : "memory");
}

#define XBUF (8 * 128)
#define WBUF (8 * NPP)

// compute one 8-channel chunk, split in two 4-pair halves (lower reg pressure)
#define COMPUTE8(Wb, Xb)                                                       \
  _Pragma("unroll")                                                            \
  for (int k = 0; k < 8; k++) {                                                \
    const ulonglong2 xv = *(const ulonglong2*)&(Xb)[k * 128 + 4 * ln];         \
    {                                                                          \
      const float4 wA = *(const float4*)&(Wb)[k * NPP + 8 * wrp];              \
      unsigned long long w0 = pack2(wA.x), w1 = pack2(wA.y);                   \
      unsigned long long w2 = pack2(wA.z), w3 = pack2(wA.w);                   \
      ffma2(acc[0][0], w0, xv.x); ffma2(acc[0][1], w0, xv.y);                  \
      ffma2(acc[1][0], w1, xv.x); ffma2(acc[1][1], w1, xv.y);                  \
      ffma2(acc[2][0], w2, xv.x); ffma2(acc[2][1], w2, xv.y);                  \
      ffma2(acc[3][0], w3, xv.x); ffma2(acc[3][1], w3, xv.y);                  \
    }                                                                          \
    {                                                                          \
      const float4 wB = *(const float4*)&(Wb)[k * NPP + 8 * wrp + 4];          \
      unsigned long long w4 = pack2(wB.x), w5 = pack2(wB.y);                   \
      unsigned long long w6 = pack2(wB.z), w7 = pack2(wB.w);                   \
      ffma2(acc[4][0], w4, xv.x); ffma2(acc[4][1], w4, xv.y);                  \
      ffma2(acc[5][0], w5, xv.x); ffma2(acc[5][1], w5, xv.y);                  \
      ffma2(acc[6][0], w6, xv.x); ffma2(acc[6][1], w6, xv.y);                  \
      ffma2(acc[7][0], w7, xv.x); ffma2(acc[7][1], w7, xv.y);                  \
    }                                                                          \
  }

// issue loads of channel-chunk j into ring buffer j&3 (conv: X + W via cp.async)
#define ISSUE_CHUNK(j, XSTRIDE)                                                \
  do {                                                                         \
    int _b = (j) & 3, _c0 = (j) * 8;                                           \
    if (hasx) cpa16(xd0 + _b * (XBUF * 4), xsrc + (size_t)_c0 * (XSTRIDE));    \
    cpa4(wda0 + _b * (WBUF * 4), wsa + _c0);                                   \
    if (hasb) cpa4(wdb0 + _b * (WBUF * 4), wsb + _c0);                         \
  } while (0)

// W-only issue (fused: X goes via TMA)
#define ISSUE_W(j, CW)                                                         \
  do {                                                                         \
    int _b = (j) & 3, _c0 = (j) * 8;                                           \
    cpa4(wda0 + _b * (WBUF * 4), wsa + _c0);                                   \
    if (hasb) cpa4(wdb0 + _b * (WBUF * 4), wsb + _c0);                         \
  } while (0)

// ---------------- conv body: 66 pairs x 128 px, 4-deep cp.async ring ---------
template <int C, int SS>
__device__ __forceinline__ void conv_body(const float* __restrict__ X,
                                          const float* __restrict__ W,
                                          const float* __restrict__ bias,
                                          float* __restrict__ Og,
                                          int n, int px0,
                                          float* Ws, float* Xs) {
  const int tid = threadIdx.x;
  const int wrp = tid >> 5, ln = tid & 31;

  unsigned long long acc[8][2];
#pragma unroll
  for (int a = 0; a < 8; a++) {
    int p = 8 * wrp + a;
    unsigned long long pk = pack2((p < NP) ? bias[p] : 0.0f);
    acc[a][0] = pk; acc[a][1] = pk;
  }

  const bool hasx = tid < 256;
  const int ch_ = tid >> 5, t_ = tid & 31;
  const unsigned xd0 = su32(&Xs[ch_ * 128 + 4 * t_]);
  const float* xsrc = X + (size_t)n * C * SS + px0 + (size_t)ch_ * SS + 4 * t_;

  const int ka = tid / 66, pa = tid - 66 * ka;
  const int sb_ = tid + 288;
  const bool hasb = sb_ < 528;
  const int kb = sb_ / 66, pb = sb_ - 66 * kb;
  const unsigned wda0 = su32(&Ws[ka * NPP + pa]);
  const unsigned wdb0 = su32(&Ws[kb * NPP + pb]);
  const float* wsa = W + pa * C + ka;
  const float* wsb = W + pb * C + kb;

  if (tid < 192) {
    int b = tid / 48, r = tid - 48 * b;
    int k = r / 6, p = 66 + (r - 6 * k);
    Ws[b * WBUF + k * NPP + p] = 0.0f;
  }

  ISSUE_CHUNK(0, SS); CPA_COMMIT();
  ISSUE_CHUNK(1, SS); CPA_COMMIT();
  ISSUE_CHUNK(2, SS); CPA_COMMIT();

  const int NIT = C / 8;
  for (int i = 0; i < NIT; i++) {
    CPA_WAIT(2);
    __syncthreads();
    {
      const float* Wb = Ws + (i & 3) * WBUF;
      const float* Xb = Xs + (i & 3) * XBUF;
      COMPUTE8(Wb, Xb);
    }
    if (i + 3 < NIT) ISSUE_CHUNK(i + 3, SS);
    CPA_COMMIT();
  }

  float* On = Og + (size_t)n * NP * SS + px0 + 4 * ln;
#pragma unroll
  for (int a = 0; a < 8; a++) {
    int p = 8 * wrp + a;
    if (p < NP) {
      ulonglong2 v;
      v.x = acc[a][0]; v.y = acc[a][1];
      *(ulonglong2*)&On[(size_t)p * SS] = v;
    }
  }
}

// ---------------- merged conv for stages 0..2 ----------------
__global__ __launch_bounds__(288, 3) void conv_all(
    const float* __restrict__ s0, const float* __restrict__ s1,
    const float* __restrict__ s2, const float* __restrict__ w0,
    const float* __restrict__ w1, const float* __restrict__ w2,
    const float* __restrict__ b0, const float* __restrict__ b1,
    const float* __restrict__ b2) {
  __shared__ __align__(16) float Ws[4 * WBUF];
  __shared__ __align__(16) float Xs[4 * XBUF];
  int bid = blockIdx.x;
  if (bid < 64) {
    conv_body<512, 32 * 32>(s0, w0, b0, g_O0, bid >> 3, (bid & 7) << 7, Ws, Xs);
  } else if (bid < 320) {
    int q = bid - 64;
    conv_body<256, 64 * 64>(s1, w1, b1, g_O1, q >> 5, (q & 31) << 7, Ws, Xs);
  } else {
    int q = bid - 320;
    conv_body<128, 128 * 128>(s2, w2, b2, g_O2, q >> 7, (q & 127) << 7, Ws, Xs);
  }
}

// ---------------- fused: stage3 conv + bilinear pyramid sum + popc vote ------
// X tiles arrive via TMA (tensormap dims {256,256,512}: z = n*64 + channel).
__global__ __launch_bounds__(288, 3) void fused_kernel(
    const __grid_constant__ CUtensorMap tmap, const float* __restrict__ W,
    const float* __restrict__ bias, float* __restrict__ out) {
  __shared__ __align__(16) float Ws[4 * WBUF];
  __shared__ __align__(1024) float Xs[4 * XBUF];  // TMA dst; signs later
  __shared__ __align__(16) float sO2[NP * 120];   // 6 rows x stride 20 (16 data)
  __shared__ __align__(16) float sO1[NP * 48];    // 4 rows x 12
  __shared__ __align__(16) float sO0[NP * 24];    // 3 rows x 8
  __shared__ __align__(8) unsigned long long sBar[4];

  const int tid = threadIdx.x;
  const int wrp = tid >> 5, ln = tid & 31;
  const int n = blockIdx.y;
  const int ty = blockIdx.x >> 4, tx = blockIdx.x & 15;
  const int y0 = ty << 3, x0 = tx << 4;

  // ---- W slot addressing (cp.async ring, unchanged) ----
  const int ka = tid / 66, pa = tid - 66 * ka;
  const int sb_ = tid + 288;
  const bool hasb = sb_ < 528;
  const int kb = sb_ / 66, pb = sb_ - 66 * kb;
  const unsigned wda0 = su32(&Ws[ka * NPP + pa]);
  const unsigned wdb0 = su32(&Ws[kb * NPP + pb]);
  const float* wsa = W + pa * 64 + ka;
  const float* wsb = W + pb * 64 + kb;

  const unsigned xsm0 = su32(&Xs[0]);
  const unsigned bar0 = su32(&sBar[0]);
  const int z0 = n * 64;

  // init mbarriers + preload X chunks 0..2 via TMA (tid 0 only)
  if (tid == 0) {
#pragma unroll
    for (int b = 0; b < 4; b++) MBAR_INIT(bar0 + 8 * b, 1);
    asm volatile("fence.proxy.async.shared::cta;" ::: "memory");
#pragma unroll
    for (int j = 0; j < 3; j++) {
      MBAR_EXPECT(bar0 + 8 * j, 4096);
      tma3d(xsm0 + j * (XBUF * 4), &tmap, x0, y0, z0 + 8 * j, bar0 + 8 * j);
    }
  }

  // W preloads (groups 0..2)
  ISSUE_W(0, 64); CPA_COMMIT();
  ISSUE_W(1, 64); CPA_COMMIT();
  ISSUE_W(2, 64); CPA_COMMIT();

  // ---- sO staging (group 3) ----
  const int by2 = (y0 >> 1) - 1, a2 = 8 * tx - 4;
  const int by1 = (y0 >> 2) - 1, a1 = 4 * tx - 4;
  const int by0 = (y0 >> 3) - 1;
  const int bx0 = 2 * tx - 1, a0x = bx0 & ~3, off0 = bx0 & 3;
  const float* s2g = g_O2 + (size_t)n * NP * 16384;
  const float* s1g = g_O1 + (size_t)n * NP * 4096;
  const float* s0g = g_O0 + (size_t)n * NP * 1024;

  if (tx >= 1 && tx <= 14) {
    for (int i = tid; i < NP * 24; i += 288) {         // O2: 6 rows x 4 chunks
      int p = i / 24, r = i - p * 24;
      int rr = r >> 2, c4 = (r & 3) << 2;
      int sy = min(max(by2 + rr, 0), 127);
      cpa16(su32(&sO2[p * 120 + rr * 20 + c4]), s2g + p * 16384 + sy * 128 + a2 + c4);
    }
    for (int i = tid; i < NP * 12; i += 288) {         // O1: 4 rows x 3 chunks
      int p = i / 12, r = i - p * 12;
      int rr = r / 3, c4 = (r - rr * 3) << 2;
      int sy = min(max(by1 + rr, 0), 63);
      cpa16(su32(&sO1[p * 48 + rr * 12 + c4]), s1g + p * 4096 + sy * 64 + a1 + c4);
    }
    for (int i = tid; i < NP * 6; i += 288) {          // O0: 3 rows x 2 chunks
      int p = i / 6, r = i - p * 6;
      int rr = r >> 1, c4 = (r & 1) << 2;
      int sy = min(max(by0 + rr, 0), 31);
      cpa16(su32(&sO0[p * 24 + rr * 8 + c4]), s0g + p * 1024 + sy * 32 + a0x + c4);
    }
  } else {  // edge tiles: scalar clamped staging (same layouts)
    for (int i = tid; i < NP * 96; i += 288) {
      int p = i / 96, r = i - p * 96;
      int rr = r >> 4, c = r & 15;
      int sy = min(max(by2 + rr, 0), 127);
      int sx = min(max(a2 + c, 0), 127);
      cpa4(su32(&sO2[p * 120 + rr * 20 + c]), s2g + p * 16384 + sy * 128 + sx);
    }
    for (int i = tid; i < NP * 48; i += 288) {
      int p = i / 48, r = i - p * 48;
      int rr = r / 12, c = r - rr * 12;
      int sy = min(max(by1 + rr, 0), 63);
      int sx = min(max(a1 + c, 0), 63);
      cpa4(su32(&sO1[p * 48 + rr * 12 + c]), s1g + p * 4096 + sy * 64 + sx);
    }
    for (int i = tid; i < NP * 24; i += 288) {
      int p = i / 24, r = i - p * 24;
      int rr = r >> 3, c = r & 7;
      int sy = min(max(by0 + rr, 0), 31);
      int sx = min(max(a0x + c, 0), 31);
      cpa4(su32(&sO0[p * 24 + rr * 8 + c]), s0g + p * 1024 + sy * 32 + sx);
    }
  }
  CPA_COMMIT();   // group 3 = staging

  // zero the weight pad slots of all 4 buffers
  if (tid < 192) {
    int b = tid / 48, r = tid - 48 * b;
    int k = r / 6, p = 66 + (r - 6 * k);
    Ws[b * WBUF + k * NPP + p] = 0.0f;
  }

  __syncthreads();  // mbarrier init visible to all before first wait

  // ---- stage3 GEMM mainloop (C=64): TMA X ring + cp.async W ring ----
  unsigned long long acc[8][2];
#pragma unroll
  for (int a = 0; a < 8; a++) {
    int p = 8 * wrp + a;
    unsigned long long pk = pack2((p < NP) ? bias[p] : 0.0f);
    acc[a][0] = pk; acc[a][1] = pk;
  }

  for (int i = 0; i < 8; i++) {
    MBAR_WAIT(bar0 + 8 * (i & 3), (i >> 2) & 1);
    CPA_WAIT(2);
    __syncthreads();
    {
      const float* Wb = Ws + (i & 3) * WBUF;
      const float* Xb = Xs + (i & 3) * XBUF;
      COMPUTE8(Wb, Xb);
    }
    if (i + 3 < 8) {
      ISSUE_W(i + 3, 64);
      if (tid == 0) {
        int b = (i + 3) & 3;
        MBAR_EXPECT(bar0 + 8 * b, 4096);
        tma3d(xsm0 + b * (XBUF * 4), &tmap, x0, y0, z0 + 8 * (i + 3), bar0 + 8 * b);
      }
    }
    CPA_COMMIT();
  }
  __syncthreads();  // all compute done; Xs ring now dead -> reuse for signs

  // ---- epilogue: separable bilinear (quad-shared taps) + sign bytes ----
  {
    const int r = ln >> 2, qc = ln & 3;
    const int ry2 = c_RY[r];      const float wy2 = c_WY[r];
    const int ry1 = c_RY[8 + r];  const float wy1 = c_WY[8 + r];
    const int ry0 = c_RY[16 + r]; const float wy0 = c_WY[16 + r];
    const int w0qc = (qc + 1) >> 1;       // {0,1,1,2}
    const float fx0adj = (qc & 1) ? 0.5f : 0.0f;

    const int   LX2[4] = {0, 1, 1, 2};
    const float FX2[4] = {.75f, .25f, .75f, .25f};
    const int   LX1[4] = {0, 0, 1, 1};
    const float FX1[4] = {.625f, .875f, .125f, .375f};
    const float FX0[4] = {.5625f, .6875f, .8125f, .9375f};

    const int o2 = ry2 * 20 + 3 + 2 * qc;
    const int o1 = ry1 * 12 + 3 + qc;
    const int o0 = ry0 * 8 + off0 + w0qc;

    unsigned by[4] = {0, 0, 0, 0};
#pragma unroll
    for (int a = 0; a < 8; a++) {
      int p = 8 * wrp + a;
      float v[4];
      float2 u0 = unpack2(acc[a][0]), u1 = unpack2(acc[a][1]);
      v[0] = u0.x; v[1] = u0.y; v[2] = u1.x; v[3] = u1.y;
      if (p < NP) {
        const float* A2 = &sO2[p * 120 + o2];
        float t2[4];
#pragma unroll
        for (int t = 0; t < 4; t++) t2[t] = A2[t] + wy2 * (A2[t + 20] - A2[t]);
        const float* A1 = &sO1[p * 48 + o1];
        float t1[3];
#pragma unroll
        for (int t = 0; t < 3; t++) t1[t] = A1[t] + wy1 * (A1[t + 12] - A1[t]);
        const float* A0 = &sO0[p * 24 + o0];
        float t0a = A0[0] + wy0 * (A0[8] - A0[0]);
        float t0b = A0[1] + wy0 * (A0[9] - A0[1]);
#pragma unroll
        for (int q = 0; q < 4; q++) {
          v[q] += t2[LX2[q]] + FX2[q] * (t2[LX2[q] + 1] - t2[LX2[q]]);
          v[q] += t1[LX1[q]] + FX1[q] * (t1[LX1[q] + 1] - t1[LX1[q]]);
          float f0 = FX0[q] - fx0adj;
          v[q] += t0a + f0 * (t0b - t0a);
        }
      }
#pragma unroll
      for (int q = 0; q < 4; q++) by[q] |= ((v[q] > 0.0f) ? 1u : 0u) << a;
    }
    unsigned* sS32 = (unsigned*)Xs;
    sS32[wrp * 32 + ln] = by[0] | (by[1] << 8) | (by[2] << 16) | (by[3] << 24);
  }
  __syncthreads();

  // ---- vote via popcount against constant masks, coalesced store ----
  if (tid < 128) {
    const unsigned char* sb8 = (const unsigned char*)Xs;
    unsigned b0 = sb8[tid],           b1 = sb8[128 + tid];
    unsigned b2 = sb8[256 + tid],     b3 = sb8[384 + tid];
    unsigned b4 = sb8[512 + tid],     b5 = sb8[640 + tid];
    unsigned b6 = sb8[768 + tid],     b7 = sb8[896 + tid];
    unsigned b8 = sb8[1024 + tid];
    unsigned sw0 = b0 | (b1 << 8) | (b2 << 16) | (b3 << 24);
    unsigned sw1 = b4 | (b5 << 8) | (b6 << 16) | (b7 << 24);
    unsigned sw2 = b8;
    int row = tid >> 4, col = tid & 15;
    float* op = out + (size_t)n * 12 * 65536 + (y0 + row) * 256 + (x0 + col);
#pragma unroll
    for (int k = 0; k < 12; k++) {
      int4 A = c_MA[k];
      int4 B = c_MB[k];
      int cnt = __popc(sw0 & (unsigned)A.x) + __popc(sw1 & (unsigned)A.y) +
                __popc(sw2 & (unsigned)A.z) - __popc(sw0 & (unsigned)A.w) -
                __popc(sw1 & (unsigned)B.x) - __popc(sw2 & (unsigned)B.y) + k;
      op[(size_t)k << 16] = (float)cnt;
    }
  }
}

// ---------------- launcher ----------------
typedef CUresult (*EncodeTiledFn)(
    CUtensorMap*, CUtensorMapDataType, cuuint32_t, void*,
    const cuuint64_t*, const cuuint64_t*, const cuuint32_t*, const cuuint32_t*,
    CUtensorMapInterleave, CUtensorMapSwizzle, CUtensorMapL2promotion,
    CUtensorMapFloatOOBfill);

extern "C" void kernel_launch(void* const* d_in, const int* in_sizes, int n_in,
                              void* d_out, int out_size) {
  const float* st[4] = {0, 0, 0, 0};
  const float* w[4] = {0, 0, 0, 0};
  const float* bb[4] = {0, 0, 0, 0};
  int bc = 0;
  for (int i = 0; i < n_in; i++) {
    switch (in_sizes[i]) {
      case 4194304:  st[0] = (const float*)d_in[i]; break;  // 8*512*32*32
      case 8388608:  st[1] = (const float*)d_in[i]; break;  // 8*256*64*64
      case 16777216: st[2] = (const float*)d_in[i]; break;  // 8*128*128*128
      case 33554432: st[3] = (const float*)d_in[i]; break;  // 8*64*256*256
      case 33792: w[0] = (const float*)d_in[i]; break;      // 66*512
      case 16896: w[1] = (const float*)d_in[i]; break;      // 66*256
      case 8448:  w[2] = (const float*)d_in[i]; break;      // 66*128
      case 4224:  w[3] = (const float*)d_in[i]; break;      // 66*64
      case 66:
        if (bc < 4) bb[bc++] = (const float*)d_in[i];       // b0..b3 in order
        break;
      default: break;  // last_only (==1 always per setup_inputs)
    }
  }

  // tensormap for stage3 X: dims {256 cols, 256 rows, 512 (n*64+ch)}
  static EncodeTiledFn enc = nullptr;
  if (!enc) {
    void* p = nullptr;
    cudaDriverEntryPointQueryResult qr;
    cudaGetDriverEntryPoint("cuTensorMapEncodeTiled", &p, cudaEnableDefault, &qr);
    enc = (EncodeTiledFn)p;
  }
  CUtensorMap tmap;
  {
    cuuint64_t dims[3] = {256, 256, 512};
    cuuint64_t strides[2] = {256 * 4, 65536 * 4};
    cuuint32_t box[3] = {16, 8, 8};
    cuuint32_t estr[3] = {1, 1, 1};
    enc(&tmap, CU_TENSOR_MAP_DATA_TYPE_FLOAT32, 3, (void*)st[3],
        dims, strides, box, estr,
        CU_TENSOR_MAP_INTERLEAVE_NONE, CU_TENSOR_MAP_SWIZZLE_NONE,
        CU_TENSOR_MAP_L2_PROMOTION_L2_128B, CU_TENSOR_MAP_FLOAT_OOB_FILL_NONE);
  }

  // prefer max shared carveout so 3 fused CTAs fit (idempotent, no alloc)
  cudaFuncSetAttribute(fused_kernel,
                       cudaFuncAttributePreferredSharedMemoryCarveout, 100);
  cudaFuncSetAttribute(conv_all,
                       cudaFuncAttributePreferredSharedMemoryCarveout, 100);

  conv_all<<<1344, 288>>>(st[0], st[1], st[2], w[0], w[1], w[2],
                          bb[0], bb[1], bb[2]);
  fused_kernel<<<dim3(512, 8), 288>>>(tmap, w[3], bb[3], (float*)d_out);
}